// round 1
// baseline (speedup 1.0000x reference)
#include <cuda_runtime.h>
#include <math.h>

#define T_ 64
#define B_ 16
#define S_ 400
#define E_ 128
#define H_ 256
#define H2_ 512
#define G_ 768
#define HC_ 896
#define DV_ 50000
#define EXT_ 50
#define DVE_ 50050

// -------- scratch (__device__ globals; no allocation allowed) --------
__device__ __align__(16) float d_encp[S_*B_*H2_];    // enc @ W_h^T + b_attn
__device__ __align__(16) float d_hidden[B_*H_];
__device__ __align__(16) float d_s1[B_*H_];
__device__ __align__(16) float d_cov[B_*S_];
__device__ __align__(16) float d_cvs[T_*B_*H2_];     // ctx per step
__device__ __align__(16) float d_hcat[T_*B_*HC_];
__device__ __align__(16) float d_u[T_*B_*H_];
__device__ __align__(16) float d_g[T_*B_];
__device__ __align__(16) float d_logits[(size_t)T_*B_*DV_];

__device__ __forceinline__ float sigm(float x){ return 1.f/(1.f+expf(-x)); }
__device__ __forceinline__ float warpSum(float v){
    #pragma unroll
    for (int o=16;o;o>>=1) v += __shfl_down_sync(0xffffffffu, v, o);
    return v;
}
__device__ __forceinline__ float warpMax(float v){
    #pragma unroll
    for (int o=16;o;o>>=1) v = fmaxf(v, __shfl_down_sync(0xffffffffu, v, o));
    return v;
}

// -------- generic NT GEMM: C[M,N] = A[M,K] @ W[N,K]^T + bias, optional tanh --------
// requires M % 64 == 0, K % 16 == 0. N arbitrary.
__global__ void gemm_nt(const float* __restrict__ A, const float* __restrict__ W,
                        const float* __restrict__ bias, float* __restrict__ C,
                        int M, int N, int K, int op)
{
    __shared__ float As[16][65];
    __shared__ float Wsm[16][65];
    int tid = threadIdx.x;                 // 256 threads
    int m0 = blockIdx.y << 6, n0 = blockIdx.x << 6;
    int tx = tid & 15, ty = tid >> 4;
    float acc[4][4] = {};
    for (int k0 = 0; k0 < K; k0 += 16) {
        #pragma unroll
        for (int i = 0; i < 4; i++) {
            int idx = tid + (i << 8);      // 0..1023
            int m  = idx >> 4;             // 0..63
            int kk = idx & 15;
            As[kk][m] = A[(size_t)(m0 + m) * K + k0 + kk];
            int n = n0 + m;
            Wsm[kk][m] = (n < N) ? W[(size_t)n * K + k0 + kk] : 0.f;
        }
        __syncthreads();
        #pragma unroll
        for (int kk = 0; kk < 16; kk++) {
            float a[4], b[4];
            #pragma unroll
            for (int i = 0; i < 4; i++) a[i] = As[kk][ty*4 + i];
            #pragma unroll
            for (int j = 0; j < 4; j++) b[j] = Wsm[kk][tx*4 + j];
            #pragma unroll
            for (int i = 0; i < 4; i++)
                #pragma unroll
                for (int j = 0; j < 4; j++)
                    acc[i][j] += a[i] * b[j];
        }
        __syncthreads();
    }
    #pragma unroll
    for (int i = 0; i < 4; i++) {
        int row = m0 + ty*4 + i;
        #pragma unroll
        for (int j = 0; j < 4; j++) {
            int col = n0 + tx*4 + j;
            if (col < N) {
                float v = acc[i][j] + (bias ? bias[col] : 0.f);
                if (op) v = tanhf(v);
                C[(size_t)row * N + col] = v;
            }
        }
    }
}

// -------- GRU1: grid (8, B), 128 threads. s1 = blend(GRU(emb_t, hidden)) --------
__global__ void gru1_kernel(const float* __restrict__ emb, const float* __restrict__ ymask,
                            const float* __restrict__ Wih, const float* __restrict__ Whh,
                            const float* __restrict__ bih, const float* __restrict__ bhh,
                            int t)
{
    int q = blockIdx.x, b = blockIdx.y;
    __shared__ float xs[E_];
    __shared__ float hsm[H_];
    __shared__ float gx[96], gh[96];
    int tid = threadIdx.x;
    for (int i = tid; i < E_; i += 128) xs[i]  = emb[((size_t)t*B_ + b)*E_ + i];
    for (int i = tid; i < H_; i += 128) hsm[i] = d_hidden[b*H_ + i];
    __syncthreads();
    int warp = tid >> 5, lane = tid & 31;
    for (int i = 0; i < 24; i++) {
        int lr = warp*24 + i;                            // 0..95
        int row = (lr >> 5) * H_ + q*32 + (lr & 31);     // gate*256 + col
        float ax = 0.f, ah = 0.f;
        for (int k = lane; k < E_; k += 32) ax += Wih[(size_t)row*E_ + k] * xs[k];
        for (int k = lane; k < H_; k += 32) ah += Whh[(size_t)row*H_ + k] * hsm[k];
        ax = warpSum(ax); ah = warpSum(ah);
        if (lane == 0) { gx[lr] = ax + bih[row]; gh[lr] = ah + bhh[row]; }
    }
    __syncthreads();
    if (tid < 32) {
        int j = q*32 + tid;
        float r = sigm(gx[tid]      + gh[tid]);
        float z = sigm(gx[32 + tid] + gh[32 + tid]);
        float n = tanhf(gx[64 + tid] + r * gh[64 + tid]);
        float h = hsm[j];
        float o = (1.f - z) * n + z * h;
        float ym = ymask[t*B_ + b];
        d_s1[b*H_ + j] = ym * o + (1.f - ym) * h;
    }
}

// -------- attention: grid (B), 512 threads. sW + scores + softmax + cov + ctx --------
__global__ void attn_kernel(const float* __restrict__ enc, const float* __restrict__ xmask,
                            const float* __restrict__ Ws_w, const float* __restrict__ Wc,
                            const float* __restrict__ Vatt,
                            float* __restrict__ waw_out, float* __restrict__ covs_out,
                            int t)
{
    int b = blockIdx.x;
    int tid = threadIdx.x, warp = tid >> 5, lane = tid & 31;   // 16 warps
    __shared__ float s1s[H_];
    __shared__ float sW[H2_];
    __shared__ float sc[S_];
    __shared__ float red[16];
    __shared__ float smax, ssum;

    for (int i = tid; i < H_; i += 512) s1s[i] = d_s1[b*H_ + i];
    __syncthreads();

    // sW[k] = s1 . Ws_w[k,:]   (warp per row, coalesced weight reads)
    for (int i = 0; i < 32; i++) {
        int k = warp*32 + i;
        float a = 0.f;
        for (int j = lane; j < H_; j += 32) a += s1s[j] * Ws_w[(size_t)k*H_ + j];
        a = warpSum(a);
        if (lane == 0) sW[k] = a;
    }
    __syncthreads();

    // scores: warp per source position
    for (int i = 0; i < 25; i++) {
        int s = warp*25 + i;
        float cov_s = d_cov[b*S_ + s];
        float xm = xmask[s*B_ + b];
        float acc = 0.f;
        size_t base = ((size_t)s*B_ + b) * H2_;
        for (int k = lane; k < H2_; k += 32) {
            float v = d_encp[base + k] + sW[k] + cov_s * Wc[k];
            acc += Vatt[k] * tanhf(v) * xm;
        }
        acc = warpSum(acc);
        if (lane == 0) {
            sc[s] = (xm == 0.f) ? -1e9f : acc;
            covs_out[((size_t)t*B_ + b)*S_ + s] = cov_s;
        }
    }
    __syncthreads();

    // softmax over S
    float mv = (tid < S_) ? sc[tid] : -3.4e38f;
    mv = warpMax(mv);
    if (lane == 0) red[warp] = mv;
    __syncthreads();
    if (tid < 32) {
        float x = (tid < 16) ? red[tid] : -3.4e38f;
        x = warpMax(x);
        if (tid == 0) smax = x;
    }
    __syncthreads();
    float ev = 0.f;
    if (tid < S_) { ev = expf(sc[tid] - smax); sc[tid] = ev; }
    float sv = warpSum(ev);
    if (lane == 0) red[warp] = sv;
    __syncthreads();
    if (tid < 32) {
        float x = (tid < 16) ? red[tid] : 0.f;
        x = warpSum(x);
        if (tid == 0) ssum = x;
    }
    __syncthreads();
    if (tid < S_) {
        float a = sc[tid] / ssum;
        sc[tid] = a;
        waw_out[((size_t)t*B_ + b)*S_ + tid] = a;
        d_cov[b*S_ + tid] += a;
    }
    __syncthreads();

    // ctx[k] = sum_s attn[s] * enc[s,b,k]   (float4, 4-way s-split within warp)
    {
        int sl = tid & 3;       // s lane
        int kq = tid >> 2;      // 0..127 -> 4 floats each
        float4 acc4 = make_float4(0.f, 0.f, 0.f, 0.f);
        for (int s = sl; s < S_; s += 4) {
            const float4 evv = *(const float4*)&enc[((size_t)s*B_ + b)*H2_ + kq*4];
            float a = sc[s];
            acc4.x += a * evv.x; acc4.y += a * evv.y;
            acc4.z += a * evv.z; acc4.w += a * evv.w;
        }
        #pragma unroll
        for (int o = 1; o < 4; o <<= 1) {
            acc4.x += __shfl_xor_sync(0xffffffffu, acc4.x, o);
            acc4.y += __shfl_xor_sync(0xffffffffu, acc4.y, o);
            acc4.z += __shfl_xor_sync(0xffffffffu, acc4.z, o);
            acc4.w += __shfl_xor_sync(0xffffffffu, acc4.w, o);
        }
        if (sl == 0)
            *(float4*)&d_cvs[((size_t)t*B_ + b)*H2_ + kq*4] = acc4;
    }
}

// -------- GRU2: grid (8, B), 128 threads. hidden = blend(GRU(ctx, s1)) --------
__global__ void gru2_kernel(const float* __restrict__ ymask,
                            const float* __restrict__ Wih, const float* __restrict__ Whh,
                            const float* __restrict__ bih, const float* __restrict__ bhh,
                            float* __restrict__ hs_out, int t)
{
    int q = blockIdx.x, b = blockIdx.y;
    __shared__ float xs[H2_];
    __shared__ float hsm[H_];
    __shared__ float gx[96], gh[96];
    int tid = threadIdx.x;
    for (int i = tid; i < H2_; i += 128) xs[i]  = d_cvs[((size_t)t*B_ + b)*H2_ + i];
    for (int i = tid; i < H_;  i += 128) hsm[i] = d_s1[b*H_ + i];
    __syncthreads();
    int warp = tid >> 5, lane = tid & 31;
    for (int i = 0; i < 24; i++) {
        int lr = warp*24 + i;
        int row = (lr >> 5) * H_ + q*32 + (lr & 31);
        float ax = 0.f, ah = 0.f;
        for (int k = lane; k < H2_; k += 32) ax += Wih[(size_t)row*H2_ + k] * xs[k];
        for (int k = lane; k < H_;  k += 32) ah += Whh[(size_t)row*H_  + k] * hsm[k];
        ax = warpSum(ax); ah = warpSum(ah);
        if (lane == 0) { gx[lr] = ax + bih[row]; gh[lr] = ah + bhh[row]; }
    }
    __syncthreads();
    if (tid < 32) {
        int j = q*32 + tid;
        float r = sigm(gx[tid]      + gh[tid]);
        float z = sigm(gx[32 + tid] + gh[32 + tid]);
        float n = tanhf(gx[64 + tid] + r * gh[64 + tid]);
        float h = hsm[j];                 // base is s1
        float o = (1.f - z) * n + z * h;
        float ym = ymask[t*B_ + b];
        float v = ym * o + (1.f - ym) * h;
        d_hidden[b*H_ + j] = v;
        hs_out[((size_t)t*B_ + b)*H_ + j] = v;
    }
}

// -------- build hcat = [hs | ctx | emb] and g = sigmoid(hcat . Wp + b) --------
__global__ void hcat_g_kernel(const float* __restrict__ hs_out, const float* __restrict__ emb,
                              const float* __restrict__ Wpw, const float* __restrict__ Wpb)
{
    int r = blockIdx.x;            // 0..1023
    int tid = threadIdx.x;         // 256
    __shared__ float red[8];
    float p = 0.f;
    for (int i = tid; i < HC_; i += 256) {
        float v;
        if (i < H_)        v = hs_out[(size_t)r*H_ + i];
        else if (i < H_+H2_) v = d_cvs[(size_t)r*H2_ + (i - H_)];
        else               v = emb[(size_t)r*E_ + (i - H_ - H2_)];
        d_hcat[(size_t)r*HC_ + i] = v;
        p += v * Wpw[i];
    }
    p = warpSum(p);
    int warp = tid >> 5, lane = tid & 31;
    if (lane == 0) red[warp] = p;
    __syncthreads();
    if (tid == 0) {
        float s = 0.f;
        #pragma unroll
        for (int i = 0; i < 8; i++) s += red[i];
        d_g[r] = sigm(s + Wpb[0]);
    }
}

// -------- softmax over vocab + write g * y_dec, zero ext region --------
__global__ void softmax_kernel(float* __restrict__ ypred)
{
    int r = blockIdx.x, tid = threadIdx.x;    // 512 threads
    const float* row = d_logits + (size_t)r * DV_;
    float* orow = ypred + (size_t)r * DVE_;
    __shared__ float red[16];
    __shared__ float sM, sZ;
    int warp = tid >> 5, lane = tid & 31;

    float m = -3.4e38f;
    for (int v = tid; v < DV_; v += 512) m = fmaxf(m, row[v]);
    m = warpMax(m);
    if (lane == 0) red[warp] = m;
    __syncthreads();
    if (tid < 32) {
        float x = (tid < 16) ? red[tid] : -3.4e38f;
        x = warpMax(x);
        if (tid == 0) sM = x;
    }
    __syncthreads();
    float Mv = sM;
    float s = 0.f;
    for (int v = tid; v < DV_; v += 512) s += expf(row[v] - Mv);
    s = warpSum(s);
    if (lane == 0) red[warp] = s;
    __syncthreads();
    if (tid < 32) {
        float x = (tid < 16) ? red[tid] : 0.f;
        x = warpSum(x);
        if (tid == 0) sZ = x;
    }
    __syncthreads();
    float coef = d_g[r] / sZ;
    for (int v = tid; v < DV_; v += 512) orow[v] = expf(row[v] - Mv) * coef;
    if (tid < EXT_) orow[DV_ + tid] = 0.f;
}

// -------- pointer scatter: ypred[r, x_index[s,b]] += (1-g) * waw --------
__global__ void scatter_kernel(const int* __restrict__ xidx,
                               const float* __restrict__ waw_out,
                               float* __restrict__ ypred)
{
    int r = blockIdx.x;             // t*B+b
    int b = r % B_;
    int tid = threadIdx.x;          // 128
    float g1 = 1.f - d_g[r];
    for (int s = tid; s < S_; s += 128) {
        int idx = xidx[s*B_ + b];
        float w = waw_out[(size_t)r*S_ + s];
        atomicAdd(&ypred[(size_t)r*DVE_ + idx], g1 * w);
    }
}

extern "C" void kernel_launch(void* const* d_in, const int* in_sizes, int n_in,
                              void* d_out, int out_size)
{
    const float* emb    = (const float*)d_in[0];
    const float* enc    = (const float*)d_in[1];
    const float* inis   = (const float*)d_in[2];
    const float* xmask  = (const float*)d_in[3];
    const float* ymask  = (const float*)d_in[4];
    const int*   xidx   = (const int*)  d_in[5];
    // d_in[6] = max_ext_len (compile-time constant here)
    const float* inicov = (const float*)d_in[7];
    const float* W_h    = (const float*)d_in[8];
    const float* W_s    = (const float*)d_in[9];
    const float* W_c    = (const float*)d_in[10];
    const float* b_attn = (const float*)d_in[11];
    const float* Vatt   = (const float*)d_in[12];
    const float* g1Wih  = (const float*)d_in[13];
    const float* g1Whh  = (const float*)d_in[14];
    const float* g1bih  = (const float*)d_in[15];
    const float* g1bhh  = (const float*)d_in[16];
    const float* g2Wih  = (const float*)d_in[17];
    const float* g2Whh  = (const float*)d_in[18];
    const float* g2bih  = (const float*)d_in[19];
    const float* g2bhh  = (const float*)d_in[20];
    const float* V1w    = (const float*)d_in[21];
    const float* V1b    = (const float*)d_in[22];
    const float* V2w    = (const float*)d_in[23];
    const float* V2b    = (const float*)d_in[24];
    const float* Wpw    = (const float*)d_in[25];
    const float* Wpb    = (const float*)d_in[26];

    float* out = (float*)d_out;
    float* ypred    = out;
    float* hs_out   = out + (size_t)T_*B_*DVE_;
    float* waw_out  = hs_out + (size_t)T_*B_*H_;
    float* covs_out = waw_out + (size_t)T_*B_*S_;

    float *p_encp, *p_hcat, *p_u, *p_logits;
    cudaGetSymbolAddress((void**)&p_encp,   d_encp);
    cudaGetSymbolAddress((void**)&p_hcat,   d_hcat);
    cudaGetSymbolAddress((void**)&p_u,      d_u);
    cudaGetSymbolAddress((void**)&p_logits, d_logits);

    cudaMemcpyToSymbolAsync(d_hidden, inis,   B_*H_*sizeof(float), 0, cudaMemcpyDeviceToDevice, 0);
    cudaMemcpyToSymbolAsync(d_cov,    inicov, B_*S_*sizeof(float), 0, cudaMemcpyDeviceToDevice, 0);

    // enc_proj = enc @ W_h^T + b_attn   (M=6400, N=512, K=512)
    gemm_nt<<<dim3(H2_/64, (S_*B_)/64), 256>>>(enc, W_h, b_attn, p_encp, S_*B_, H2_, H2_, 0);

    for (int t = 0; t < T_; t++) {
        gru1_kernel<<<dim3(8, B_), 128>>>(emb, ymask, g1Wih, g1Whh, g1bih, g1bhh, t);
        attn_kernel<<<B_, 512>>>(enc, xmask, W_s, W_c, Vatt, waw_out, covs_out, t);
        gru2_kernel<<<dim3(8, B_), 128>>>(ymask, g2Wih, g2Whh, g2bih, g2bhh, hs_out, t);
    }

    hcat_g_kernel<<<T_*B_, 256>>>(hs_out, emb, Wpw, Wpb);
    // u = tanh(hcat @ V1^T + b)   (M=1024, N=256, K=896)
    gemm_nt<<<dim3(H_/64, (T_*B_)/64), 256>>>(p_hcat, V1w, V1b, p_u, T_*B_, H_, HC_, 1);
    // logits = u @ V2^T + b       (M=1024, N=50000, K=256)
    gemm_nt<<<dim3((DV_+63)/64, (T_*B_)/64), 256>>>(p_u, V2w, V2b, p_logits, T_*B_, DV_, H_, 0);
    softmax_kernel<<<T_*B_, 512>>>(ypred);
    scatter_kernel<<<T_*B_, 128>>>(xidx, waw_out, ypred);
}

// round 8
// speedup vs baseline: 2.3069x; 2.3069x over previous
#include <cuda_runtime.h>
#include <math.h>

#define T_ 64
#define B_ 16
#define S_ 400
#define E_ 128
#define H_ 256
#define H2_ 512
#define G_ 768
#define HC_ 896
#define DV_ 50000
#define EXT_ 50
#define DVE_ 50050

// -------- scratch (__device__ globals; no allocation allowed) --------
__device__ __align__(16) float d_encp[S_*B_*H2_];    // enc @ W_h^T + b_attn
__device__ __align__(16) float d_gx1[T_*B_*G_];      // emb @ g1Wih^T + g1bih
__device__ __align__(16) float d_hid[B_*H_];
__device__ __align__(16) float d_s1g[B_*H_];
__device__ __align__(16) float d_sWg[B_*H2_];
__device__ __align__(16) float d_scg[B_*S_];
__device__ __align__(16) float d_cvs[T_*B_*H2_];     // ctx per step
__device__ __align__(16) float d_hcat[T_*B_*HC_];
__device__ __align__(16) float d_u[T_*B_*H_];
__device__ __align__(16) float d_g[T_*B_];
__device__ __align__(16) float d_logits[(size_t)T_*B_*DV_];

__device__ __forceinline__ float sigm(float x){ return 1.f/(1.f+__expf(-x)); }
// overflow-safe fast tanh via MUFU ex2
__device__ __forceinline__ float tfast(float x){
    float a = fabsf(x);
    float e = __expf(-2.f*a);
    float t = (1.f - e) / (1.f + e);
    return copysignf(t, x);
}
__device__ __forceinline__ float warpSum(float v){
    #pragma unroll
    for (int o=16;o;o>>=1) v += __shfl_down_sync(0xffffffffu, v, o);
    return v;
}
__device__ __forceinline__ float warpMax(float v){
    #pragma unroll
    for (int o=16;o;o>>=1) v = fmaxf(v, __shfl_down_sync(0xffffffffu, v, o));
    return v;
}

// arrive defaults to .release, wait to .acquire -> cross-CTA global handoff is ordered
#define CLUSTER_SYNC() do { \
    asm volatile("barrier.cluster.arrive.aligned;" ::: "memory"); \
    asm volatile("barrier.cluster.wait.aligned;" ::: "memory"); \
} while(0)

// ===================== GEMM: C[M,N] = A[M,K] @ W[N,K]^T + bias (opt tanh) ==========
// 128x128 tile, 256 threads, 8x8 microtile. Requires M%128==0, K%8==0.
__global__ void gemm128(const float* __restrict__ A, const float* __restrict__ W,
                        const float* __restrict__ bias, float* __restrict__ C,
                        int M, int N, int K, int op)
{
    __shared__ float As[8][132];
    __shared__ float Ws[8][132];
    int tid = threadIdx.x;
    int m0 = blockIdx.y*128, n0 = blockIdx.x*128;
    int ty = tid>>4, tx = tid&15;
    int lr = tid>>1;
    int lk = (tid&1)*4;
    float acc[8][8] = {};
    for (int k0 = 0; k0 < K; k0 += 8) {
        float4 a4 = *(const float4*)&A[(size_t)(m0+lr)*K + k0 + lk];
        int n = n0 + lr;
        float4 w4 = (n < N) ? *(const float4*)&W[(size_t)n*K + k0 + lk]
                            : make_float4(0.f,0.f,0.f,0.f);
        As[lk+0][lr]=a4.x; As[lk+1][lr]=a4.y; As[lk+2][lr]=a4.z; As[lk+3][lr]=a4.w;
        Ws[lk+0][lr]=w4.x; Ws[lk+1][lr]=w4.y; Ws[lk+2][lr]=w4.z; Ws[lk+3][lr]=w4.w;
        __syncthreads();
        #pragma unroll
        for (int kk = 0; kk < 8; kk++) {
            float4 a0 = *(const float4*)&As[kk][ty*8];
            float4 a1 = *(const float4*)&As[kk][ty*8+4];
            float4 w0 = *(const float4*)&Ws[kk][tx*8];
            float4 w1 = *(const float4*)&Ws[kk][tx*8+4];
            float a[8] = {a0.x,a0.y,a0.z,a0.w,a1.x,a1.y,a1.z,a1.w};
            float w[8] = {w0.x,w0.y,w0.z,w0.w,w1.x,w1.y,w1.z,w1.w};
            #pragma unroll
            for (int i=0;i<8;i++)
                #pragma unroll
                for (int j=0;j<8;j++)
                    acc[i][j] += a[i]*w[j];
        }
        __syncthreads();
    }
    #pragma unroll
    for (int i=0;i<8;i++){
        int row = m0 + ty*8 + i;
        #pragma unroll
        for (int j=0;j<8;j++){
            int col = n0 + tx*8 + j;
            if (col < N){
                float v = acc[i][j] + (bias ? bias[col] : 0.f);
                if (op) v = tanhf(v);
                C[(size_t)row*N + col] = v;
            }
        }
    }
}

// ===================== persistent recurrence: 16 clusters x 8 CTAs x 256 thr =======
__global__ void __cluster_dims__(8,1,1) recurrence_kernel(
    const float* __restrict__ emb, const float* __restrict__ enc,
    const float* __restrict__ inis, const float* __restrict__ xmask,
    const float* __restrict__ ymask, const float* __restrict__ inicov,
    const float* __restrict__ Ws_w, const float* __restrict__ Wc,
    const float* __restrict__ Vatt,
    const float* __restrict__ g1Whh, const float* __restrict__ g1bhh,
    const float* __restrict__ g2Wih, const float* __restrict__ g2Whh,
    const float* __restrict__ g2bih, const float* __restrict__ g2bhh,
    float* __restrict__ hs_out, float* __restrict__ waw_out,
    float* __restrict__ covs_out)
{
    int r = blockIdx.x & 7;          // cluster rank
    int b = blockIdx.x >> 3;         // batch element
    int tid = threadIdx.x, warp = tid>>5, lane = tid&31;

    __shared__ float sh_hid[H_], sh_s1[H_], sh_ctx[H2_], sh_sW[H2_];
    __shared__ float sh_Wc[H2_], sh_V[H2_];
    __shared__ float sh_att[S_];
    __shared__ float sh_cov[50];
    __shared__ float sh_g1[96], sh_gx2[96], sh_gh2[96];
    __shared__ float red_[8];
    __shared__ float sh_max, sh_sum;

    for (int i = tid; i < H2_; i += 256) { sh_Wc[i] = Wc[i]; sh_V[i] = Vatt[i]; }
    if (tid < 50) sh_cov[tid] = inicov[b*S_ + r*50 + tid];
    if (tid < 32) d_hid[b*H_ + r*32 + tid] = inis[b*H_ + r*32 + tid];

    for (int t = 0; t < T_; t++) {
        CLUSTER_SYNC();   // full hidden visible
        float ym = ymask[t*B_ + b];

        // ---- Phase A: GRU1 hidden-path + gate combine ----
        for (int i = tid; i < H_; i += 256) sh_hid[i] = d_hid[b*H_ + i];
        __syncthreads();
        #pragma unroll
        for (int it = 0; it < 12; it++) {
            int lr2 = warp + 8*it;                       // 0..95
            int row = (lr2>>5)*H_ + r*32 + (lr2&31);
            float a = 0.f;
            for (int k = lane; k < H_; k += 32) a += g1Whh[(size_t)row*H_+k]*sh_hid[k];
            a = warpSum(a);
            if (lane == 0) sh_g1[lr2] = a + g1bhh[row];
        }
        __syncthreads();
        if (tid < 32) {
            int j = r*32 + tid;
            const float* gx = &d_gx1[((size_t)t*B_ + b)*G_];
            float rr = sigm(gx[j]        + sh_g1[tid]);
            float zz = sigm(gx[H_ + j]   + sh_g1[32+tid]);
            float nn = tfast(gx[2*H_ + j] + rr*sh_g1[64+tid]);
            float h = sh_hid[j];
            float o = (1.f - zz)*nn + zz*h;
            d_s1g[b*H_ + j] = ym*o + (1.f - ym)*h;
        }
        CLUSTER_SYNC();

        // ---- Phase B1: sW = W_s @ s1 ----
        for (int i = tid; i < H_; i += 256) sh_s1[i] = d_s1g[b*H_ + i];
        __syncthreads();
        #pragma unroll
        for (int it = 0; it < 8; it++) {
            int k = r*64 + warp + 8*it;
            float a = 0.f;
            for (int j2 = lane; j2 < H_; j2 += 32) a += Ws_w[(size_t)k*H_+j2]*sh_s1[j2];
            a = warpSum(a);
            if (lane == 0) d_sWg[b*H2_ + k] = a;
        }
        CLUSTER_SYNC();

        // ---- Phase B2: scores ----
        for (int i = tid; i < H2_; i += 256) sh_sW[i] = d_sWg[b*H2_ + i];
        __syncthreads();
        for (int it = 0; it < 7; it++) {
            int sl_ = warp + 8*it;
            if (sl_ < 50) {
                int s = r*50 + sl_;
                float covv = sh_cov[sl_];
                float xm = xmask[s*B_ + b];
                float acc = 0.f;
                size_t base = ((size_t)s*B_ + b)*H2_;
                for (int k = lane; k < H2_; k += 32) {
                    float v = d_encp[base+k] + sh_sW[k] + covv*sh_Wc[k];
                    acc += sh_V[k]*tfast(v);
                }
                acc = warpSum(acc)*xm;
                if (lane == 0) {
                    d_scg[b*S_ + s] = (xm == 0.f) ? -1e9f : acc;
                    covs_out[((size_t)t*B_ + b)*S_ + s] = covv;
                }
            }
        }
        CLUSTER_SYNC();

        // ---- Phase B3: local softmax over S ----
        for (int i = tid; i < S_; i += 256) sh_att[i] = d_scg[b*S_ + i];
        __syncthreads();
        float m = -3.4e38f;
        for (int i = tid; i < S_; i += 256) m = fmaxf(m, sh_att[i]);
        m = warpMax(m);
        if (lane == 0) red_[warp] = m;
        __syncthreads();
        if (tid == 0) { float x = red_[0]; for (int i=1;i<8;i++) x = fmaxf(x, red_[i]); sh_max = x; }
        __syncthreads();
        float ssum = 0.f;
        for (int i = tid; i < S_; i += 256) { float e = __expf(sh_att[i]-sh_max); sh_att[i] = e; ssum += e; }
        ssum = warpSum(ssum);
        if (lane == 0) red_[warp] = ssum;
        __syncthreads();
        if (tid == 0) { float x = 0.f; for (int i=0;i<8;i++) x += red_[i]; sh_sum = x; }
        __syncthreads();
        float inv = 1.f / sh_sum;
        if (tid < 50) {
            int s = r*50 + tid;
            float a = sh_att[s]*inv;
            waw_out[((size_t)t*B_ + b)*S_ + s] = a;
            sh_cov[tid] += a;
        }

        // ---- Phase B4: ctx slice (64 k per CTA) ----
        {
            int sl_ = tid & 15, kq = tid >> 4;
            int k = r*64 + kq*4;
            float4 acc4 = make_float4(0.f,0.f,0.f,0.f);
            for (int s = sl_; s < S_; s += 16) {
                float a = sh_att[s]*inv;
                const float4 e4 = *(const float4*)&enc[((size_t)s*B_ + b)*H2_ + k];
                acc4.x += a*e4.x; acc4.y += a*e4.y; acc4.z += a*e4.z; acc4.w += a*e4.w;
            }
            #pragma unroll
            for (int o = 8; o; o >>= 1) {
                acc4.x += __shfl_xor_sync(0xffffffffu, acc4.x, o);
                acc4.y += __shfl_xor_sync(0xffffffffu, acc4.y, o);
                acc4.z += __shfl_xor_sync(0xffffffffu, acc4.z, o);
                acc4.w += __shfl_xor_sync(0xffffffffu, acc4.w, o);
            }
            if (sl_ == 0) *(float4*)&d_cvs[((size_t)t*B_ + b)*H2_ + k] = acc4;
        }
        CLUSTER_SYNC();

        // ---- Phase C: GRU2 ----
        for (int i = tid; i < H2_; i += 256) sh_ctx[i] = d_cvs[((size_t)t*B_ + b)*H2_ + i];
        __syncthreads();
        #pragma unroll
        for (int it = 0; it < 12; it++) {
            int lr2 = warp + 8*it;
            int row = (lr2>>5)*H_ + r*32 + (lr2&31);
            float ax = 0.f, ah = 0.f;
            for (int k = lane; k < H2_; k += 32) ax += g2Wih[(size_t)row*H2_+k]*sh_ctx[k];
            for (int k = lane; k < H_;  k += 32) ah += g2Whh[(size_t)row*H_+k]*sh_s1[k];
            ax = warpSum(ax); ah = warpSum(ah);
            if (lane == 0) { sh_gx2[lr2] = ax + g2bih[row]; sh_gh2[lr2] = ah + g2bhh[row]; }
        }
        __syncthreads();
        if (tid < 32) {
            int j = r*32 + tid;
            float rr = sigm(sh_gx2[tid]     + sh_gh2[tid]);
            float zz = sigm(sh_gx2[32+tid]  + sh_gh2[32+tid]);
            float nn = tfast(sh_gx2[64+tid] + rr*sh_gh2[64+tid]);
            float h = sh_s1[j];
            float o = (1.f - zz)*nn + zz*h;
            float v = ym*o + (1.f - ym)*h;
            d_hid[b*H_ + j] = v;
            hs_out[((size_t)t*B_ + b)*H_ + j] = v;
        }
    }
}

// -------- hcat = [hs | ctx | emb], g = sigmoid(hcat . Wp + b) --------
__global__ void hcat_g_kernel(const float* __restrict__ hs_out, const float* __restrict__ emb,
                              const float* __restrict__ Wpw, const float* __restrict__ Wpb)
{
    int r = blockIdx.x;
    int tid = threadIdx.x;    // 256
    __shared__ float red[8];
    float p = 0.f;
    for (int i = tid; i < HC_; i += 256) {
        float v;
        if (i < H_)          v = hs_out[(size_t)r*H_ + i];
        else if (i < H_+H2_) v = d_cvs[(size_t)r*H2_ + (i - H_)];
        else                 v = emb[(size_t)r*E_ + (i - H_ - H2_)];
        d_hcat[(size_t)r*HC_ + i] = v;
        p += v * Wpw[i];
    }
    p = warpSum(p);
    int warp = tid >> 5, lane = tid & 31;
    if (lane == 0) red[warp] = p;
    __syncthreads();
    if (tid == 0) {
        float s = 0.f;
        #pragma unroll
        for (int i = 0; i < 8; i++) s += red[i];
        d_g[r] = sigm(s + Wpb[0]);
    }
}

// -------- softmax over vocab (float4 loads, float2 stores) + fused scatter --------
// ypred row base is r*DVE_ floats; DVE_=50050 is even but NOT /4 -> float2 only.
__global__ void softmax_scatter_kernel(float* __restrict__ ypred,
                                       const int* __restrict__ xidx,
                                       const float* __restrict__ waw_out)
{
    int r = blockIdx.x, tid = threadIdx.x;    // 512 threads
    const float4* row4 = (const float4*)(d_logits + (size_t)r * DV_);
    float* orow = ypred + (size_t)r * DVE_;
    float2* orow2 = (float2*)orow;            // 8B-aligned: r*DVE_ is even
    __shared__ float red[16];
    __shared__ float sM, sZ;
    int warp = tid >> 5, lane = tid & 31;
    const int NV4 = DV_ / 4;    // 12500

    float m = -3.4e38f;
    for (int v = tid; v < NV4; v += 512) {
        float4 x = row4[v];
        m = fmaxf(m, fmaxf(fmaxf(x.x, x.y), fmaxf(x.z, x.w)));
    }
    m = warpMax(m);
    if (lane == 0) red[warp] = m;
    __syncthreads();
    if (tid < 32) {
        float x = (tid < 16) ? red[tid] : -3.4e38f;
        x = warpMax(x);
        if (tid == 0) sM = x;
    }
    __syncthreads();
    float Mv = sM;
    float s = 0.f;
    for (int v = tid; v < NV4; v += 512) {
        float4 x = row4[v];
        s += __expf(x.x - Mv) + __expf(x.y - Mv) + __expf(x.z - Mv) + __expf(x.w - Mv);
    }
    s = warpSum(s);
    if (lane == 0) red[warp] = s;
    __syncthreads();
    if (tid < 32) {
        float x = (tid < 16) ? red[tid] : 0.f;
        x = warpSum(x);
        if (tid == 0) sZ = x;
    }
    __syncthreads();
    float gv = d_g[r];
    float coef = gv / sZ;
    for (int v = tid; v < NV4; v += 512) {
        float4 x = row4[v];
        float2 o0, o1;
        o0.x = __expf(x.x - Mv) * coef;
        o0.y = __expf(x.y - Mv) * coef;
        o1.x = __expf(x.z - Mv) * coef;
        o1.y = __expf(x.w - Mv) * coef;
        orow2[v*2]   = o0;
        orow2[v*2+1] = o1;
    }
    if (tid < EXT_) orow[DV_ + tid] = 0.f;
    __syncthreads();   // block's own global stores visible before RMW below

    // fused pointer scatter: this block owns row r of ypred
    int b = r % B_;
    float g1 = 1.f - gv;
    for (int s2 = tid; s2 < S_; s2 += 512) {
        int idx = xidx[s2*B_ + b];
        float w = waw_out[(size_t)r*S_ + s2];
        atomicAdd(&orow[idx], g1 * w);
    }
}

extern "C" void kernel_launch(void* const* d_in, const int* in_sizes, int n_in,
                              void* d_out, int out_size)
{
    const float* emb    = (const float*)d_in[0];
    const float* enc    = (const float*)d_in[1];
    const float* inis   = (const float*)d_in[2];
    const float* xmask  = (const float*)d_in[3];
    const float* ymask  = (const float*)d_in[4];
    const int*   xidx   = (const int*)  d_in[5];
    const float* inicov = (const float*)d_in[7];
    const float* W_h    = (const float*)d_in[8];
    const float* W_s    = (const float*)d_in[9];
    const float* W_c    = (const float*)d_in[10];
    const float* b_attn = (const float*)d_in[11];
    const float* Vatt   = (const float*)d_in[12];
    const float* g1Wih  = (const float*)d_in[13];
    const float* g1Whh  = (const float*)d_in[14];
    const float* g1bih  = (const float*)d_in[15];
    const float* g1bhh  = (const float*)d_in[16];
    const float* g2Wih  = (const float*)d_in[17];
    const float* g2Whh  = (const float*)d_in[18];
    const float* g2bih  = (const float*)d_in[19];
    const float* g2bhh  = (const float*)d_in[20];
    const float* V1w    = (const float*)d_in[21];
    const float* V1b    = (const float*)d_in[22];
    const float* V2w    = (const float*)d_in[23];
    const float* V2b    = (const float*)d_in[24];
    const float* Wpw    = (const float*)d_in[25];
    const float* Wpb    = (const float*)d_in[26];

    float* out = (float*)d_out;
    float* ypred    = out;
    float* hs_out   = out + (size_t)T_*B_*DVE_;
    float* waw_out  = hs_out + (size_t)T_*B_*H_;
    float* covs_out = waw_out + (size_t)T_*B_*S_;

    float *p_encp, *p_gx1, *p_hcat, *p_u, *p_logits;
    cudaGetSymbolAddress((void**)&p_encp,   d_encp);
    cudaGetSymbolAddress((void**)&p_gx1,    d_gx1);
    cudaGetSymbolAddress((void**)&p_hcat,   d_hcat);
    cudaGetSymbolAddress((void**)&p_u,      d_u);
    cudaGetSymbolAddress((void**)&p_logits, d_logits);

    // enc_proj = enc @ W_h^T + b_attn   (M=6400, N=512, K=512)
    gemm128<<<dim3(H2_/128, (S_*B_)/128), 256>>>(enc, W_h, b_attn, p_encp, S_*B_, H2_, H2_, 0);
    // gx1 = emb @ g1Wih^T + g1bih       (M=1024, N=768, K=128)
    gemm128<<<dim3(G_/128, (T_*B_)/128), 256>>>(emb, g1Wih, g1bih, p_gx1, T_*B_, G_, E_, 0);

    // whole recurrence: one persistent clustered kernel
    recurrence_kernel<<<dim3(B_*8), 256>>>(
        emb, enc, inis, xmask, ymask, inicov,
        W_s, W_c, Vatt, g1Whh, g1bhh,
        g2Wih, g2Whh, g2bih, g2bhh,
        hs_out, waw_out, covs_out);

    hcat_g_kernel<<<T_*B_, 256>>>(hs_out, emb, Wpw, Wpb);
    // u = tanh(hcat @ V1^T + b)   (M=1024, N=256, K=896)
    gemm128<<<dim3(H_/128, (T_*B_)/128), 256>>>(p_hcat, V1w, V1b, p_u, T_*B_, H_, HC_, 1);
    // logits = u @ V2^T + b       (M=1024, N=50000, K=256)
    gemm128<<<dim3((DV_+127)/128, (T_*B_)/128), 256>>>(p_u, V2w, V2b, p_logits, T_*B_, DV_, H_, 0);
    softmax_scatter_kernel<<<T_*B_, 512>>>(ypred, xidx, waw_out);
}

// round 16
// speedup vs baseline: 2.4650x; 1.0685x over previous
#include <cuda_runtime.h>
#include <math.h>
#include <stdint.h>

#define T_ 64
#define B_ 16
#define S_ 400
#define E_ 128
#define H_ 256
#define H2_ 512
#define G_ 768
#define HC_ 896
#define DV_ 50000
#define EXT_ 50
#define DVE_ 50050

// -------- scratch (__device__ globals; no allocation allowed) --------
__device__ __align__(16) float d_encp[S_*B_*H2_];
__device__ __align__(16) float d_gx1[T_*B_*G_];
__device__ __align__(16) float d_hid[B_*H_];
__device__ __align__(16) float d_s1g[B_*H_];
__device__ __align__(16) float d_sWg[B_*H2_];
__device__ __align__(16) float d_scg[B_*S_];
__device__ __align__(16) float d_cvs[T_*B_*H2_];
__device__ __align__(16) float d_hcat[T_*B_*HC_];
__device__ __align__(16) float d_u[T_*B_*H_];
__device__ __align__(16) float d_g[T_*B_];
__device__ __align__(16) float d_logits[(size_t)T_*B_*DV_];

__device__ __forceinline__ float sigm(float x){ return 1.f/(1.f+__expf(-x)); }
__device__ __forceinline__ float tfast(float x){           // accurate fast tanh
    float a = fabsf(x);
    float e = __expf(-2.f*a);
    float t = (1.f - e) / (1.f + e);
    return copysignf(t, x);
}
__device__ __forceinline__ float warpSum(float v){
    #pragma unroll
    for (int o=16;o;o>>=1) v += __shfl_down_sync(0xffffffffu, v, o);
    return v;
}
__device__ __forceinline__ float warpMax(float v){
    #pragma unroll
    for (int o=16;o;o>>=1) v = fmaxf(v, __shfl_down_sync(0xffffffffu, v, o));
    return v;
}
__device__ __forceinline__ uint32_t f2tf(float f){
    uint32_t u; asm("cvt.rna.tf32.f32 %0, %1;" : "=r"(u) : "f"(f)); return u;
}
__device__ __forceinline__ void mma_tf32(float* c, const uint32_t* a, const uint32_t* b){
    asm volatile(
        "mma.sync.aligned.m16n8k8.row.col.f32.tf32.tf32.f32 "
        "{%0,%1,%2,%3}, {%4,%5,%6,%7}, {%8,%9}, {%0,%1,%2,%3};"
        : "+f"(c[0]), "+f"(c[1]), "+f"(c[2]), "+f"(c[3])
        : "r"(a[0]), "r"(a[1]), "r"(a[2]), "r"(a[3]), "r"(b[0]), "r"(b[1]));
}

#define CLUSTER_SYNC() do { \
    asm volatile("barrier.cluster.arrive.aligned;" ::: "memory"); \
    asm volatile("barrier.cluster.wait.aligned;" ::: "memory"); \
} while(0)

// ============ tensor-core GEMM: C[M,N] = A[M,K] @ W[N,K]^T + bias (opt tanh) ======
// tf32 hi/lo split (3-term) -> ~fp32 accuracy. Block 64x64, 256 thr, k-tile 32.
// Requires M%64==0, K%32==0. N arbitrary (tail guarded).
__global__ void __launch_bounds__(256) gemm_tc(
    const float* __restrict__ A, const float* __restrict__ W,
    const float* __restrict__ bias, float* __restrict__ C,
    int M, int N, int K, int op)
{
    __shared__ float Ah[64][36], Al[64][36], Bh[64][36], Bl[64][36];
    int tid = threadIdx.x;
    int m0 = blockIdx.y*64, n0 = blockIdx.x*64;
    int warp = tid>>5, lane = tid&31;
    int gid = lane>>2, tg = lane&3;
    int mw = warp&1, nw = warp>>1;      // 2 x 4 warp grid, warp tile 32x16
    float acc[2][2][4] = {};

    for (int kt = 0; kt < K; kt += 32){
        #pragma unroll
        for (int x = tid; x < 512; x += 256){
            int row = x>>3, j = x&7;
            float4 v = *(const float4*)&A[(size_t)(m0+row)*K + kt + j*4];
            float fa[4] = {v.x, v.y, v.z, v.w};
            #pragma unroll
            for (int q = 0; q < 4; q++){
                uint32_t hu = f2tf(fa[q]); float hf = __uint_as_float(hu);
                Ah[row][j*4+q] = hf;
                Al[row][j*4+q] = __uint_as_float(f2tf(fa[q]-hf));
            }
            int n = n0 + row;
            float4 w = (n < N) ? *(const float4*)&W[(size_t)n*K + kt + j*4]
                               : make_float4(0.f,0.f,0.f,0.f);
            float fb[4] = {w.x, w.y, w.z, w.w};
            #pragma unroll
            for (int q = 0; q < 4; q++){
                uint32_t hu = f2tf(fb[q]); float hf = __uint_as_float(hu);
                Bh[row][j*4+q] = hf;
                Bl[row][j*4+q] = __uint_as_float(f2tf(fb[q]-hf));
            }
        }
        __syncthreads();
        #pragma unroll
        for (int kb = 0; kb < 32; kb += 8){
            uint32_t ah[2][4], al[2][4], bh[2][2], bl[2][2];
            #pragma unroll
            for (int mt = 0; mt < 2; mt++){
                int rw = mw*32 + mt*16;
                ah[mt][0] = __float_as_uint(Ah[rw+gid  ][kb+tg  ]);
                ah[mt][1] = __float_as_uint(Ah[rw+gid+8][kb+tg  ]);
                ah[mt][2] = __float_as_uint(Ah[rw+gid  ][kb+tg+4]);
                ah[mt][3] = __float_as_uint(Ah[rw+gid+8][kb+tg+4]);
                al[mt][0] = __float_as_uint(Al[rw+gid  ][kb+tg  ]);
                al[mt][1] = __float_as_uint(Al[rw+gid+8][kb+tg  ]);
                al[mt][2] = __float_as_uint(Al[rw+gid  ][kb+tg+4]);
                al[mt][3] = __float_as_uint(Al[rw+gid+8][kb+tg+4]);
            }
            #pragma unroll
            for (int nt = 0; nt < 2; nt++){
                int cl = nw*16 + nt*8;
                bh[nt][0] = __float_as_uint(Bh[cl+gid][kb+tg  ]);
                bh[nt][1] = __float_as_uint(Bh[cl+gid][kb+tg+4]);
                bl[nt][0] = __float_as_uint(Bl[cl+gid][kb+tg  ]);
                bl[nt][1] = __float_as_uint(Bl[cl+gid][kb+tg+4]);
            }
            #pragma unroll
            for (int mt = 0; mt < 2; mt++)
                #pragma unroll
                for (int nt = 0; nt < 2; nt++){
                    mma_tf32(acc[mt][nt], ah[mt], bh[nt]);
                    mma_tf32(acc[mt][nt], al[mt], bh[nt]);
                    mma_tf32(acc[mt][nt], ah[mt], bl[nt]);
                }
        }
        __syncthreads();
    }
    // epilogue
    #pragma unroll
    for (int mt = 0; mt < 2; mt++)
        #pragma unroll
        for (int nt = 0; nt < 2; nt++){
            int row = m0 + mw*32 + mt*16 + gid;
            int col = n0 + nw*16 + nt*8 + tg*2;
            float* cc = acc[mt][nt];
            #pragma unroll
            for (int half = 0; half < 2; half++){
                int rr = row + half*8;
                #pragma unroll
                for (int e = 0; e < 2; e++){
                    int c2 = col + e;
                    if (c2 < N){
                        float v = cc[half*2 + e] + bias[c2];
                        if (op) v = tanhf(v);
                        C[(size_t)rr*N + c2] = v;
                    }
                }
            }
        }
}

// ===================== persistent recurrence: 16 clusters x 8 CTAs x 512 thr =======
// dynamic smem: g2Wih slice [96][512] (192KB) cached once, survives L1 flushes.
__global__ void __launch_bounds__(512,1) __cluster_dims__(8,1,1) recurrence_kernel(
    const float* __restrict__ emb, const float* __restrict__ enc,
    const float* __restrict__ inis, const float* __restrict__ xmask,
    const float* __restrict__ ymask, const float* __restrict__ inicov,
    const float* __restrict__ Ws_w, const float* __restrict__ Wc,
    const float* __restrict__ Vatt,
    const float* __restrict__ g1Whh, const float* __restrict__ g1bhh,
    const float* __restrict__ g2Wih, const float* __restrict__ g2Whh,
    const float* __restrict__ g2bih, const float* __restrict__ g2bhh,
    float* __restrict__ hs_out, float* __restrict__ waw_out,
    float* __restrict__ covs_out)
{
    extern __shared__ float wWih2[];    // [96][512]
    int r = blockIdx.x & 7;
    int b = blockIdx.x >> 3;
    int tid = threadIdx.x, warp = tid>>5, lane = tid&31;

    __shared__ float sh_hid[H_], sh_s1[H_], sh_ctx[H2_], sh_sW[H2_];
    __shared__ float sh_Wc[H2_], sh_V[H2_];
    __shared__ float sh_att[S_];
    __shared__ float sh_cov[50];
    __shared__ float sh_g1[96], sh_gx2[96], sh_gh2[96];
    __shared__ float red_[16];
    __shared__ float sh_max, sh_sum;

    for (int i = tid; i < H2_; i += 512) { sh_Wc[i] = Wc[i]; sh_V[i] = Vatt[i]; }
    for (int i = tid; i < 96*H2_; i += 512){
        int row = i >> 9, k = i & 511;
        wWih2[i] = g2Wih[(size_t)((row>>5)*H_ + r*32 + (row&31))*H2_ + k];
    }
    if (tid < 50) sh_cov[tid] = inicov[b*S_ + r*50 + tid];
    if (tid < 32) d_hid[b*H_ + r*32 + tid] = inis[b*H_ + r*32 + tid];

    for (int t = 0; t < T_; t++){
        CLUSTER_SYNC();   // hidden slices visible (also covers smem init at t=0)
        float ym = ymask[t*B_ + b];

        // ---- Phase A: GRU1 hidden matvec (16 warps x 6 rows, float4) ----
        for (int i = tid; i < H_; i += 512) sh_hid[i] = d_hid[b*H_ + i];
        __syncthreads();
        #pragma unroll
        for (int it = 0; it < 6; it++){
            int lr2 = warp*6 + it;                         // 0..95
            int row = (lr2>>5)*H_ + r*32 + (lr2&31);
            const float4* w4 = (const float4*)&g1Whh[(size_t)row*H_];
            const float4* h4 = (const float4*)sh_hid;
            float a = 0.f;
            #pragma unroll
            for (int kk = lane; kk < 64; kk += 32){
                float4 w = w4[kk], h = h4[kk];
                a += w.x*h.x + w.y*h.y + w.z*h.z + w.w*h.w;
            }
            a = warpSum(a);
            if (lane == 0) sh_g1[lr2] = a + g1bhh[row];
        }
        __syncthreads();
        if (tid < 32){
            int j = r*32 + tid;
            const float* gx = &d_gx1[((size_t)t*B_ + b)*G_];
            float rr = sigm(gx[j]         + sh_g1[tid]);
            float zz = sigm(gx[H_ + j]    + sh_g1[32+tid]);
            float nn = tfast(gx[2*H_ + j] + rr*sh_g1[64+tid]);
            float h = sh_hid[j];
            float o = (1.f - zz)*nn + zz*h;
            d_s1g[b*H_ + j] = ym*o + (1.f - ym)*h;
        }
        CLUSTER_SYNC();

        // ---- Phase B1: sW = W_s @ s1 (16 warps x 4 rows) ----
        for (int i = tid; i < H_; i += 512) sh_s1[i] = d_s1g[b*H_ + i];
        __syncthreads();
        #pragma unroll
        for (int it = 0; it < 4; it++){
            int k = r*64 + warp*4 + it;
            const float4* w4 = (const float4*)&Ws_w[(size_t)k*H_];
            const float4* s4 = (const float4*)sh_s1;
            float a = 0.f;
            #pragma unroll
            for (int kk = lane; kk < 64; kk += 32){
                float4 w = w4[kk], s = s4[kk];
                a += w.x*s.x + w.y*s.y + w.z*s.z + w.w*s.w;
            }
            a = warpSum(a);
            if (lane == 0) d_sWg[b*H2_ + k] = a;
        }
        CLUSTER_SYNC();

        // ---- Phase B2: scores (accurate tfast tanh, float4) ----
        for (int i = tid; i < H2_; i += 512) sh_sW[i] = d_sWg[b*H2_ + i];
        __syncthreads();
        for (int it = 0; it < 4; it++){
            int sl_ = warp + 16*it;
            if (sl_ < 50){
                int s = r*50 + sl_;
                float covv = sh_cov[sl_];
                float xm = xmask[s*B_ + b];
                const float4* e4  = (const float4*)&d_encp[((size_t)s*B_ + b)*H2_];
                const float4* sw4 = (const float4*)sh_sW;
                const float4* wc4 = (const float4*)sh_Wc;
                const float4* v4  = (const float4*)sh_V;
                float acc = 0.f;
                #pragma unroll
                for (int kk = lane; kk < 128; kk += 32){
                    float4 e = e4[kk], sw = sw4[kk], wc = wc4[kk], vv = v4[kk];
                    acc += vv.x*tfast(e.x + sw.x + covv*wc.x);
                    acc += vv.y*tfast(e.y + sw.y + covv*wc.y);
                    acc += vv.z*tfast(e.z + sw.z + covv*wc.z);
                    acc += vv.w*tfast(e.w + sw.w + covv*wc.w);
                }
                acc = warpSum(acc)*xm;
                if (lane == 0){
                    d_scg[b*S_ + s] = (xm == 0.f) ? -1e9f : acc;
                    covs_out[((size_t)t*B_ + b)*S_ + s] = covv;
                }
            }
        }
        CLUSTER_SYNC();

        // ---- Phase B3: local softmax over S (512 thr) ----
        for (int i = tid; i < S_; i += 512) sh_att[i] = d_scg[b*S_ + i];
        __syncthreads();
        float m = -3.4e38f;
        for (int i = tid; i < S_; i += 512) m = fmaxf(m, sh_att[i]);
        m = warpMax(m);
        if (lane == 0) red_[warp] = m;
        __syncthreads();
        if (tid == 0){ float x = red_[0]; for (int i=1;i<16;i++) x = fmaxf(x, red_[i]); sh_max = x; }
        __syncthreads();
        float ssum = 0.f;
        for (int i = tid; i < S_; i += 512){ float e = __expf(sh_att[i]-sh_max); sh_att[i] = e; ssum += e; }
        ssum = warpSum(ssum);
        if (lane == 0) red_[warp] = ssum;
        __syncthreads();
        if (tid == 0){ float x = 0.f; for (int i=0;i<16;i++) x += red_[i]; sh_sum = x; }
        __syncthreads();
        float inv = 1.f / sh_sum;
        if (tid < 50){
            int s = r*50 + tid;
            float a = sh_att[s]*inv;
            waw_out[((size_t)t*B_ + b)*S_ + s] = a;
            sh_cov[tid] += a;
        }

        // ---- Phase B4: ctx slice (warp per float4-group of k) ----
        {
            int k = r*64 + warp*4;
            float4 acc4 = make_float4(0.f,0.f,0.f,0.f);
            for (int s = lane; s < S_; s += 32){
                float a = sh_att[s]*inv;
                const float4 e4 = *(const float4*)&enc[((size_t)s*B_ + b)*H2_ + k];
                acc4.x += a*e4.x; acc4.y += a*e4.y; acc4.z += a*e4.z; acc4.w += a*e4.w;
            }
            #pragma unroll
            for (int o = 16; o; o >>= 1){
                acc4.x += __shfl_xor_sync(0xffffffffu, acc4.x, o);
                acc4.y += __shfl_xor_sync(0xffffffffu, acc4.y, o);
                acc4.z += __shfl_xor_sync(0xffffffffu, acc4.z, o);
                acc4.w += __shfl_xor_sync(0xffffffffu, acc4.w, o);
            }
            if (lane == 0) *(float4*)&d_cvs[((size_t)t*B_ + b)*H2_ + k] = acc4;
        }
        CLUSTER_SYNC();

        // ---- Phase C: GRU2 (ctx matvec from smem-cached weights) ----
        for (int i = tid; i < H2_; i += 512) sh_ctx[i] = d_cvs[((size_t)t*B_ + b)*H2_ + i];
        __syncthreads();
        #pragma unroll
        for (int it = 0; it < 6; it++){
            int lr2 = warp*6 + it;
            int grow = (lr2>>5)*H_ + r*32 + (lr2&31);
            const float4* wi4 = (const float4*)&wWih2[lr2*H2_];
            const float4* c4  = (const float4*)sh_ctx;
            const float4* wh4 = (const float4*)&g2Whh[(size_t)grow*H_];
            const float4* s4  = (const float4*)sh_s1;
            float ax = 0.f, ah = 0.f;
            #pragma unroll
            for (int kk = lane; kk < 128; kk += 32){
                float4 w = wi4[kk], c = c4[kk];
                ax += w.x*c.x + w.y*c.y + w.z*c.z + w.w*c.w;
            }
            #pragma unroll
            for (int kk = lane; kk < 64; kk += 32){
                float4 w = wh4[kk], s = s4[kk];
                ah += w.x*s.x + w.y*s.y + w.z*s.z + w.w*s.w;
            }
            ax = warpSum(ax); ah = warpSum(ah);
            if (lane == 0){ sh_gx2[lr2] = ax + g2bih[grow]; sh_gh2[lr2] = ah + g2bhh[grow]; }
        }
        __syncthreads();
        if (tid < 32){
            int j = r*32 + tid;
            float rr = sigm(sh_gx2[tid]     + sh_gh2[tid]);
            float zz = sigm(sh_gx2[32+tid]  + sh_gh2[32+tid]);
            float nn = tfast(sh_gx2[64+tid] + rr*sh_gh2[64+tid]);
            float h = sh_s1[j];
            float o = (1.f - zz)*nn + zz*h;
            float v = ym*o + (1.f - ym)*h;
            d_hid[b*H_ + j] = v;
            hs_out[((size_t)t*B_ + b)*H_ + j] = v;
        }
    }
}

// -------- hcat = [hs | ctx | emb], g = sigmoid(hcat . Wp + b) --------
__global__ void hcat_g_kernel(const float* __restrict__ hs_out, const float* __restrict__ emb,
                              const float* __restrict__ Wpw, const float* __restrict__ Wpb)
{
    int r = blockIdx.x;
    int tid = threadIdx.x;    // 256
    __shared__ float red[8];
    float p = 0.f;
    for (int i = tid; i < HC_; i += 256){
        float v;
        if (i < H_)          v = hs_out[(size_t)r*H_ + i];
        else if (i < H_+H2_) v = d_cvs[(size_t)r*H2_ + (i - H_)];
        else                 v = emb[(size_t)r*E_ + (i - H_ - H2_)];
        d_hcat[(size_t)r*HC_ + i] = v;
        p += v * Wpw[i];
    }
    p = warpSum(p);
    int warp = tid >> 5, lane = tid & 31;
    if (lane == 0) red[warp] = p;
    __syncthreads();
    if (tid == 0){
        float s = 0.f;
        #pragma unroll
        for (int i = 0; i < 8; i++) s += red[i];
        d_g[r] = sigm(s + Wpb[0]);
    }
}

// -------- softmax over vocab (float4 loads, float2 stores) + fused scatter --------
__global__ void softmax_scatter_kernel(float* __restrict__ ypred,
                                       const int* __restrict__ xidx,
                                       const float* __restrict__ waw_out)
{
    int r = blockIdx.x, tid = threadIdx.x;    // 512 threads
    const float4* row4 = (const float4*)(d_logits + (size_t)r * DV_);
    float* orow = ypred + (size_t)r * DVE_;
    float2* orow2 = (float2*)orow;            // r*DVE_ even -> 8B aligned
    __shared__ float red[16];
    __shared__ float sM, sZ;
    int warp = tid >> 5, lane = tid & 31;
    const int NV4 = DV_ / 4;

    float m = -3.4e38f;
    for (int v = tid; v < NV4; v += 512){
        float4 x = row4[v];
        m = fmaxf(m, fmaxf(fmaxf(x.x, x.y), fmaxf(x.z, x.w)));
    }
    m = warpMax(m);
    if (lane == 0) red[warp] = m;
    __syncthreads();
    if (tid < 32){
        float x = (tid < 16) ? red[tid] : -3.4e38f;
        x = warpMax(x);
        if (tid == 0) sM = x;
    }
    __syncthreads();
    float Mv = sM;
    float s = 0.f;
    for (int v = tid; v < NV4; v += 512){
        float4 x = row4[v];
        s += __expf(x.x - Mv) + __expf(x.y - Mv) + __expf(x.z - Mv) + __expf(x.w - Mv);
    }
    s = warpSum(s);
    if (lane == 0) red[warp] = s;
    __syncthreads();
    if (tid < 32){
        float x = (tid < 16) ? red[tid] : 0.f;
        x = warpSum(x);
        if (tid == 0) sZ = x;
    }
    __syncthreads();
    float gv = d_g[r];
    float coef = gv / sZ;
    for (int v = tid; v < NV4; v += 512){
        float4 x = row4[v];
        float2 o0, o1;
        o0.x = __expf(x.x - Mv) * coef;
        o0.y = __expf(x.y - Mv) * coef;
        o1.x = __expf(x.z - Mv) * coef;
        o1.y = __expf(x.w - Mv) * coef;
        orow2[v*2]   = o0;
        orow2[v*2+1] = o1;
    }
    if (tid < EXT_) orow[DV_ + tid] = 0.f;
    __syncthreads();

    int b = r % B_;
    float g1 = 1.f - gv;
    for (int s2 = tid; s2 < S_; s2 += 512){
        int idx = xidx[s2*B_ + b];
        float w = waw_out[(size_t)r*S_ + s2];
        atomicAdd(&orow[idx], g1 * w);
    }
}

extern "C" void kernel_launch(void* const* d_in, const int* in_sizes, int n_in,
                              void* d_out, int out_size)
{
    const float* emb    = (const float*)d_in[0];
    const float* enc    = (const float*)d_in[1];
    const float* inis   = (const float*)d_in[2];
    const float* xmask  = (const float*)d_in[3];
    const float* ymask  = (const float*)d_in[4];
    const int*   xidx   = (const int*)  d_in[5];
    const float* inicov = (const float*)d_in[7];
    const float* W_h    = (const float*)d_in[8];
    const float* W_s    = (const float*)d_in[9];
    const float* W_c    = (const float*)d_in[10];
    const float* b_attn = (const float*)d_in[11];
    const float* Vatt   = (const float*)d_in[12];
    const float* g1Wih  = (const float*)d_in[13];
    const float* g1Whh  = (const float*)d_in[14];
    const float* g1bih  = (const float*)d_in[15];
    const float* g1bhh  = (const float*)d_in[16];
    const float* g2Wih  = (const float*)d_in[17];
    const float* g2Whh  = (const float*)d_in[18];
    const float* g2bih  = (const float*)d_in[19];
    const float* g2bhh  = (const float*)d_in[20];
    const float* V1w    = (const float*)d_in[21];
    const float* V1b    = (const float*)d_in[22];
    const float* V2w    = (const float*)d_in[23];
    const float* V2b    = (const float*)d_in[24];
    const float* Wpw    = (const float*)d_in[25];
    const float* Wpb    = (const float*)d_in[26];

    float* out = (float*)d_out;
    float* ypred    = out;
    float* hs_out   = out + (size_t)T_*B_*DVE_;
    float* waw_out  = hs_out + (size_t)T_*B_*H_;
    float* covs_out = waw_out + (size_t)T_*B_*S_;

    float *p_encp, *p_gx1, *p_hcat, *p_u, *p_logits;
    cudaGetSymbolAddress((void**)&p_encp,   d_encp);
    cudaGetSymbolAddress((void**)&p_gx1,    d_gx1);
    cudaGetSymbolAddress((void**)&p_hcat,   d_hcat);
    cudaGetSymbolAddress((void**)&p_u,      d_u);
    cudaGetSymbolAddress((void**)&p_logits, d_logits);

    const int RSMEM = 96*H2_*sizeof(float);   // 192KB dynamic smem
    cudaFuncSetAttribute(recurrence_kernel,
                         cudaFuncAttributeMaxDynamicSharedMemorySize, RSMEM);

    // enc_proj = enc @ W_h^T + b_attn   (M=6400, N=512, K=512)
    gemm_tc<<<dim3(H2_/64, (S_*B_)/64), 256>>>(enc, W_h, b_attn, p_encp, S_*B_, H2_, H2_, 0);
    // gx1 = emb @ g1Wih^T + g1bih       (M=1024, N=768, K=128)
    gemm_tc<<<dim3(G_/64, (T_*B_)/64), 256>>>(emb, g1Wih, g1bih, p_gx1, T_*B_, G_, E_, 0);

    // whole recurrence: one persistent clustered kernel
    recurrence_kernel<<<dim3(B_*8), 512, RSMEM>>>(
        emb, enc, inis, xmask, ymask, inicov,
        W_s, W_c, Vatt, g1Whh, g1bhh,
        g2Wih, g2Whh, g2bih, g2bhh,
        hs_out, waw_out, covs_out);

    hcat_g_kernel<<<T_*B_, 256>>>(hs_out, emb, Wpw, Wpb);
    // u = tanh(hcat @ V1^T + b)   (M=1024, N=256, K=896)
    gemm_tc<<<dim3(H_/64, (T_*B_)/64), 256>>>(p_hcat, V1w, V1b, p_u, T_*B_, H_, HC_, 1);
    // logits = u @ V2^T + b       (M=1024, N=50000, K=256)
    gemm_tc<<<dim3((DV_+63)/64, (T_*B_)/64), 256>>>(p_u, V2w, V2b, p_logits, T_*B_, DV_, H_, 0);
    softmax_scatter_kernel<<<T_*B_, 512>>>(ypred, xidx, waw_out);
}